// round 13
// baseline (speedup 1.0000x reference)
#include <cuda_runtime.h>
#include <cuda_bf16.h>
#include <cstdint>
#include <math.h>

#define VOCAB 32000
#define DMODEL 256
#define NLAYER 6
#define DS 16
#define DC 4
#define DI 512
#define DTR 16
#define LSEQ 128
#define XDW 48             // DTR + 2*DS
#define NSLAB 16

// All 16 replicas are provably identical (replica-symmetric network); compute one.
// Attention with identical replicas => softmax uniform => branch is affine with
// combined weight Wc = Wo@Wv, bias bc = Wo@bv + ob (precomputed per layer).

// ---------------- scratch (device globals; no allocation allowed) ----------
__device__ float g_h[LSEQ*DMODEL];          // residual ping
__device__ float g_h2[LSEQ*DMODEL];         // residual pong
__device__ float g_z[LSEQ*DI];
__device__ float g_u[LSEQ*DI];
__device__ float g_xdbl[NSLAB*LSEQ*XDW];
__device__ float g_gate[LSEQ*DI];
__device__ float g_wc[NLAYER*DMODEL*DMODEL]; // combined attn weights
__device__ float g_bc[NLAYER*DMODEL];        // combined attn bias
__device__ unsigned g_bar;                   // monotonic slab counter (memset per launch)

// ---------------- helpers ----------
__device__ __forceinline__ float siluf(float x) { return x / (1.f + __expf(-x)); }
__device__ __forceinline__ float softplusf(float x) { return (x > 20.f) ? x : log1pf(__expf(x)); }

__device__ __forceinline__ uint32_t packbf(float x, float y) {
    __nv_bfloat162 h = __floats2bfloat162_rn(x, y);
    return *reinterpret_cast<uint32_t*>(&h);
}

__device__ __forceinline__ void mma16(float* c, const uint32_t* a, const uint32_t* b) {
    asm volatile(
        "mma.sync.aligned.m16n8k16.row.col.f32.bf16.bf16.f32 "
        "{%0,%1,%2,%3}, {%4,%5,%6,%7}, {%8,%9}, {%0,%1,%2,%3};"
        : "+f"(c[0]), "+f"(c[1]), "+f"(c[2]), "+f"(c[3])
        : "r"(a[0]), "r"(a[1]), "r"(a[2]), "r"(a[3]), "r"(b[0]), "r"(b[1]));
}

// ---------------- prep: combine attn weights + biases + embed --------------
__global__ void k_prep(const int* __restrict__ x, const float* __restrict__ emb,
                       const float* __restrict__ aiw, const float* __restrict__ aib,
                       const float* __restrict__ aow, const float* __restrict__ aob) {
    int z = blockIdx.z;
    int tid = threadIdx.x;
    if (z < NLAYER) {
        const float* Wo = aow + (size_t)z*DMODEL*DMODEL;
        const float* Wv = aiw + (size_t)z*3*DMODEL*DMODEL + (size_t)2*DMODEL*DMODEL;
        float* Wc = g_wc + (size_t)z*DMODEL*DMODEL;
        __shared__ float sA[16][65];
        __shared__ float sW[16][64];
        int bx = blockIdx.x;
        int d0 = (bx >> 2)*64, k0 = (bx & 3)*64;
        int ty = tid >> 4, tx = tid & 15;
        float acc[4][4] = {};
        for (int e0 = 0; e0 < DMODEL; e0 += 16) {
            {
                int d = tid >> 2, e = (tid & 3)*4;
                float4 v = *reinterpret_cast<const float4*>(&Wo[(size_t)(d0+d)*DMODEL + e0 + e]);
                sA[e+0][d] = v.x; sA[e+1][d] = v.y; sA[e+2][d] = v.z; sA[e+3][d] = v.w;
            }
            {
                int e = tid >> 4, k = (tid & 15)*4;
                float4 v = *reinterpret_cast<const float4*>(&Wv[(size_t)(e0+e)*DMODEL + k0 + k]);
                sW[e][k] = v.x; sW[e][k+1] = v.y; sW[e][k+2] = v.z; sW[e][k+3] = v.w;
            }
            __syncthreads();
            #pragma unroll
            for (int e = 0; e < 16; e++) {
                float a[4], w[4];
                #pragma unroll
                for (int i = 0; i < 4; i++) a[i] = sA[e][ty*4+i];
                #pragma unroll
                for (int j = 0; j < 4; j++) w[j] = sW[e][tx*4+j];
                #pragma unroll
                for (int i = 0; i < 4; i++)
                    #pragma unroll
                    for (int j = 0; j < 4; j++) acc[i][j] += a[i]*w[j];
            }
            __syncthreads();
        }
        #pragma unroll
        for (int i = 0; i < 4; i++)
            #pragma unroll
            for (int j = 0; j < 4; j++)
                Wc[(size_t)(d0+ty*4+i)*DMODEL + k0+tx*4+j] = acc[i][j];
    } else {
        int bx = blockIdx.x;
        if (bx < NLAYER) {
            const float* Wo = aow + (size_t)bx*DMODEL*DMODEL;
            const float* bv = aib + (size_t)bx*3*DMODEL + 2*DMODEL;
            const float* ob = aob + (size_t)bx*DMODEL;
            float s = ob[tid];
            for (int e = 0; e < DMODEL; e++) s += Wo[(size_t)tid*DMODEL+e]*bv[e];
            g_bc[bx*DMODEL + tid] = s;
        } else {
            for (int idx = (bx-NLAYER)*256 + tid; idx < LSEQ*DMODEL; idx += 10*256)
                g_h[idx] = emb[(size_t)x[idx >> 8]*DMODEL + (idx & 255)];
        }
    }
}

// ---------------- tensor-core split-bf16 GEMM (near-fp32 accurate) --------
// C[M,N] = act(A[M,K] @ W[N,K]^T + bias)
// mode: 0 = store, 1 = +=, 4 = C = addsrc + result
// mode 3 = in_proj special (BM=128): n0<DI -> fused causal conv+silu -> uout;
//          n0>=DI -> store z half to zout.
// lnmode 1 = LayerNorm A rows in prologue (K == LN dim).
#define TBN 64
#define TBK 16
#define SW 12
template<int BM>
__global__ void __launch_bounds__(BM*2)
k_gemm_tc(const float* __restrict__ A, int lda,
          const float* __restrict__ W, int ldw,
          const float* __restrict__ bias,
          float* __restrict__ C, int ldc,
          int M, int N, int K, int act, int mode,
          const float* __restrict__ lnw, const float* __restrict__ lnb, int lnmode,
          const float* __restrict__ cvw, const float* __restrict__ cvb,
          float* __restrict__ uout, float* __restrict__ zout,
          const float* __restrict__ addsrc) {
    constexpr int T = BM*2;
    constexpr int AW = 2*BM*SW;
    constexpr int WW = 2*TBN*SW;
    __shared__ __align__(16) uint32_t smem[2*AW + 2*WW];
    __shared__ float sMean[BM], sRstd[BM];
    uint32_t* Ash = smem;
    uint32_t* Asl = smem + AW;
    uint32_t* Wsh = smem + 2*AW;
    uint32_t* Wsl = smem + 2*AW + WW;
    #define ASH(s,m,k) Ash[((s)*BM+(m))*SW+(k)]
    #define ASL(s,m,k) Asl[((s)*BM+(m))*SW+(k)]
    #define WSH(s,n,k) Wsh[((s)*TBN+(n))*SW+(k)]
    #define WSL(s,n,k) Wsl[((s)*TBN+(n))*SW+(k)]

    int tid = threadIdx.x;
    int wid = tid >> 5, lane = tid & 31;
    int wm = wid >> 1, wn = wid & 1;
    int g = lane >> 2, t = lane & 3;
    int m0 = blockIdx.y * BM, n0 = blockIdx.x * TBN;

    if (lnmode) {
        constexpr int NWARP = T/32;
        for (int r = wid; r < BM; r += NWARP) {
            int gm = m0 + r;
            float s = 0.f, s2 = 0.f;
            for (int k = lane*4; k < K; k += 128) {
                float4 v = *reinterpret_cast<const float4*>(&A[(size_t)gm*lda + k]);
                s  += v.x + v.y + v.z + v.w;
                s2 += v.x*v.x + v.y*v.y + v.z*v.z + v.w*v.w;
            }
            #pragma unroll
            for (int o = 16; o > 0; o >>= 1) {
                s  += __shfl_xor_sync(0xffffffffu, s, o);
                s2 += __shfl_xor_sync(0xffffffffu, s2, o);
            }
            if (lane == 0) {
                float mean = s / K;
                sMean[r] = mean;
                sRstd[r] = rsqrtf(s2 / K - mean*mean + 1e-5f);
            }
        }
        __syncthreads();
    }

    float acc[2][4][4] = {};
    constexpr int NA4 = BM*4/T;
    constexpr int NW4 = TBN*4/T;
    float4 rA[NA4], rW[NW4 ? NW4 : 1];

    auto load_tile = [&](int k0) {
        #pragma unroll
        for (int i = 0; i < NA4; i++) {
            int slot = tid + i*T;
            int m = slot >> 2;
            int gm = m0 + m, gk = k0 + (slot & 3)*4;
            float4 v = make_float4(0.f,0.f,0.f,0.f);
            if (gm < M && gk < K) {
                v = *reinterpret_cast<const float4*>(&A[(size_t)gm*lda + gk]);
                if (lnmode) {
                    float mean = sMean[m], rstd = sRstd[m];
                    float4 w4 = *reinterpret_cast<const float4*>(&lnw[gk]);
                    float4 b4 = *reinterpret_cast<const float4*>(&lnb[gk]);
                    v.x = (v.x - mean)*rstd*w4.x + b4.x;
                    v.y = (v.y - mean)*rstd*w4.y + b4.y;
                    v.z = (v.z - mean)*rstd*w4.z + b4.z;
                    v.w = (v.w - mean)*rstd*w4.w + b4.w;
                }
            }
            rA[i] = v;
        }
        #pragma unroll
        for (int i = 0; i < NW4; i++) {
            int slot = tid + i*T;
            int gn = n0 + (slot >> 2), gk = k0 + (slot & 3)*4;
            float4 v = make_float4(0.f,0.f,0.f,0.f);
            if (gn < N && gk < K)
                v = *reinterpret_cast<const float4*>(&W[(size_t)gn*ldw + gk]);
            rW[i] = v;
        }
    };
    auto store_tile = [&](int s) {
        #pragma unroll
        for (int i = 0; i < NA4; i++) {
            int slot = tid + i*T;
            int m = slot >> 2, kw = (slot & 3)*2;
            float4 v = rA[i];
            uint32_t h0 = packbf(v.x, v.y), h1 = packbf(v.z, v.w);
            __nv_bfloat162 b0 = *reinterpret_cast<__nv_bfloat162*>(&h0);
            __nv_bfloat162 b1 = *reinterpret_cast<__nv_bfloat162*>(&h1);
            ASH(s,m,kw)   = h0; ASH(s,m,kw+1) = h1;
            ASL(s,m,kw)   = packbf(v.x - __low2float(b0), v.y - __high2float(b0));
            ASL(s,m,kw+1) = packbf(v.z - __low2float(b1), v.w - __high2float(b1));
        }
        #pragma unroll
        for (int i = 0; i < NW4; i++) {
            int slot = tid + i*T;
            int n = slot >> 2, kw = (slot & 3)*2;
            float4 v = rW[i];
            uint32_t h0 = packbf(v.x, v.y), h1 = packbf(v.z, v.w);
            __nv_bfloat162 b0 = *reinterpret_cast<__nv_bfloat162*>(&h0);
            __nv_bfloat162 b1 = *reinterpret_cast<__nv_bfloat162*>(&h1);
            WSH(s,n,kw)   = h0; WSH(s,n,kw+1) = h1;
            WSL(s,n,kw)   = packbf(v.x - __low2float(b0), v.y - __high2float(b0));
            WSL(s,n,kw+1) = packbf(v.z - __low2float(b1), v.w - __high2float(b1));
        }
    };

    int nt = (K + TBK - 1) / TBK;
    load_tile(0);
    store_tile(0);
    __syncthreads();

    for (int it = 0; it < nt; it++) {
        int cur = it & 1;
        if (it + 1 < nt) load_tile((it+1) * TBK);
        uint32_t ah[2][4], al[2][4], bh[4][2], bl[4][2];
        #pragma unroll
        for (int mf = 0; mf < 2; mf++) {
            int mr = wm*32 + mf*16;
            ah[mf][0] = ASH(cur, mr + g,     t    );
            ah[mf][1] = ASH(cur, mr + 8 + g, t    );
            ah[mf][2] = ASH(cur, mr + g,     t + 4);
            ah[mf][3] = ASH(cur, mr + 8 + g, t + 4);
            al[mf][0] = ASL(cur, mr + g,     t    );
            al[mf][1] = ASL(cur, mr + 8 + g, t    );
            al[mf][2] = ASL(cur, mr + g,     t + 4);
            al[mf][3] = ASL(cur, mr + 8 + g, t + 4);
        }
        #pragma unroll
        for (int nf = 0; nf < 4; nf++) {
            int nr = wn*32 + nf*8;
            bh[nf][0] = WSH(cur, nr + g, t    );
            bh[nf][1] = WSH(cur, nr + g, t + 4);
            bl[nf][0] = WSL(cur, nr + g, t    );
            bl[nf][1] = WSL(cur, nr + g, t + 4);
        }
        #pragma unroll
        for (int mf = 0; mf < 2; mf++)
            #pragma unroll
            for (int nf = 0; nf < 4; nf++) {
                mma16(acc[mf][nf], al[mf], bh[nf]);
                mma16(acc[mf][nf], ah[mf], bl[nf]);
                mma16(acc[mf][nf], ah[mf], bh[nf]);
            }
        if (it + 1 < nt) store_tile(cur ^ 1);
        __syncthreads();
    }

    if (mode == 3 && n0 < DI) {
        float* cb2 = reinterpret_cast<float*>(smem);   // [128][68]
        #pragma unroll
        for (int mf = 0; mf < 2; mf++)
            #pragma unroll
            for (int nf = 0; nf < 4; nf++)
                #pragma unroll
                for (int e = 0; e < 4; e++) {
                    int r = wm*32 + mf*16 + g + (e >> 1)*8;
                    int c = wn*32 + nf*8 + 2*t + (e & 1);
                    cb2[r*68 + c] = acc[mf][nf][e];
                }
        __syncthreads();
        for (int idx = tid; idx < 128*TBN; idx += T) {
            int tt2 = idx >> 6, c = idx & 63;
            int ch = n0 + c;
            float s = cvb[ch];
            #pragma unroll
            for (int k = 0; k < DC; k++) {
                int tp = tt2 - (DC-1) + k;
                if (tp >= 0) s += cb2[tp*68 + c] * cvw[ch*DC + k];
            }
            uout[(size_t)tt2*DI + ch] = siluf(s);
        }
        return;
    }
    #pragma unroll
    for (int mf = 0; mf < 2; mf++)
        #pragma unroll
        for (int nf = 0; nf < 4; nf++)
            #pragma unroll
            for (int e = 0; e < 4; e++) {
                int gm = m0 + wm*32 + mf*16 + g + (e >> 1)*8;
                int gn = n0 + wn*32 + nf*8 + 2*t + (e & 1);
                if (gm < M && gn < N) {
                    float v = acc[mf][nf][e];
                    if (bias) v += bias[gn];
                    if (act == 1) v = softplusf(v);
                    size_t o = (size_t)gm*ldc + gn;
                    if (mode == 0)      C[o] = v;
                    else if (mode == 1) C[o] += v;
                    else if (mode == 4) C[o] = addsrc[o] + v;
                    else                zout[(size_t)gm*DI + (gn - DI)] = v;
                }
            }
}

// ---------------- scan mega: x_proj slab + barrier + dt + scan + gate ------
// grid 16 (= dchunk = kslab), block 512.
__global__ void __launch_bounds__(512)
k_scanmega(int layer,
           const float* __restrict__ xpw,
           const float* __restrict__ A_log, const float* __restrict__ skipD,
           const float* __restrict__ dpw, const float* __restrict__ dpb) {
    __shared__ float S[14880];
    float* sdt = S;              // [128][32]
    float* su  = S + 4096;       // [128][32]
    float* sB  = S + 8192;       // [128][16]
    float* sC  = S + 10240;      // [128][16]
    float* sX  = S + 12288;      // [128][16]
    float* sW  = S + 14336;      // [32][17]
    int cta = blockIdx.x;        // dchunk AND kslab id
    int tid = threadIdx.x;

    // ---- phase A: xdbl partial for k-slab [cta*32, cta*32+32) ----
    {
        float* sU  = S;          // [128][33] (overlays sdt/su region)
        float* sWx = S + 4224;   // [48][33]
        int kk0 = cta*32;
        for (int idx = tid; idx < LSEQ*32; idx += 512) {
            int r = idx >> 5, k = idx & 31;
            sU[r*33 + k] = g_u[(size_t)r*DI + kk0 + k];
        }
        for (int idx = tid; idx < XDW*32; idx += 512) {
            int c = idx >> 5, k = idx & 31;
            sWx[c*33 + k] = xpw[(size_t)c*DI + kk0 + k];
        }
        __syncthreads();
        int r = tid >> 2, cg = tid & 3;      // 12 cols per thread
        float acc[12] = {};
        for (int k = 0; k < 32; k++) {
            float a = sU[r*33 + k];
            #pragma unroll
            for (int j = 0; j < 12; j++)
                acc[j] += a * sWx[(cg*12 + j)*33 + k];
        }
        float* outp = g_xdbl + (size_t)cta*LSEQ*XDW + (size_t)r*XDW + cg*12;
        #pragma unroll
        for (int j = 0; j < 12; j++) outp[j] = acc[j];
        __threadfence();
        __syncthreads();
        if (tid == 0) {
            atomicAdd(&g_bar, 1u);
            while (*(volatile unsigned*)&g_bar < (unsigned)(NSLAB*(layer+1))) { }
            __threadfence();
        }
        __syncthreads();
    }

    // ---- phase B: load u chunk, sum 16 xdbl slabs ----
    for (int idx = tid; idx < LSEQ*32; idx += 512) {
        int tt = idx >> 5, dd = idx & 31;
        su[idx] = g_u[(size_t)tt*DI + cta*32 + dd];
    }
    for (int idx = tid; idx < LSEQ*XDW; idx += 512) {
        int tt = idx / XDW, c = idx - tt*XDW;
        float v = 0.f;
        #pragma unroll
        for (int sl = 0; sl < NSLAB; sl++) v += g_xdbl[(size_t)sl*LSEQ*XDW + idx];
        if (c < DTR)          sX[tt*16 + c] = v;
        else if (c < DTR+DS)  sB[tt*16 + c - DTR] = v;
        else                  sC[tt*16 + c - DTR - DS] = v;
    }
    if (tid < 32*DTR)
        sW[(tid >> 4)*17 + (tid & 15)] = dpw[(cta*32 + (tid >> 4))*DTR + (tid & 15)];
    __syncthreads();
    // dt = softplus(sX @ sW^T + dpb)
    for (int idx = tid; idx < LSEQ*32; idx += 512) {
        int tt = idx >> 5, dd = idx & 31;
        float a = dpb[cta*32 + dd];
        #pragma unroll
        for (int kk = 0; kk < DTR; kk++) a += sX[tt*16+kk] * sW[dd*17+kk];
        sdt[idx] = softplusf(a);
    }
    __syncthreads();

    // ---- phase C: scan (chunk-of-8: exp batch then FFMA-only recurrence) --
    int s = tid & 15, dl = tid >> 4;         // dl 0..31
    int d = cta*32 + dl;
    float Ads = -__expf(A_log[d*DS + s]);
    float skip = skipD[d];
    float h = 0.f;
    for (int tc = 0; tc < LSEQ; tc += 8) {
        float e[8], b[8], cc[8], uu[8];
        #pragma unroll
        for (int j = 0; j < 8; j++) {
            float dtv = sdt[(tc+j)*32 + dl];
            uu[j] = su[(tc+j)*32 + dl];
            e[j] = __expf(dtv * Ads);
            b[j] = dtv * uu[j] * sB[(tc+j)*16 + s];
            cc[j] = sC[(tc+j)*16 + s];
        }
        #pragma unroll
        for (int j = 0; j < 8; j++) {
            h = e[j]*h + b[j];
            float p = h * cc[j];
            p += __shfl_xor_sync(0xffffffffu, p, 8, 16);
            p += __shfl_xor_sync(0xffffffffu, p, 4, 16);
            p += __shfl_xor_sync(0xffffffffu, p, 2, 16);
            p += __shfl_xor_sync(0xffffffffu, p, 1, 16);
            if (s == 0) sdt[(tc+j)*32 + dl] = p + uu[j]*skip;   // recycle sdt as y
        }
    }
    __syncthreads();
    // gate = y * silu(z)
    for (int idx = tid; idx < LSEQ*32; idx += 512) {
        int tt = idx >> 5, dd = idx & 31;
        int gd = cta*32 + dd;
        float z = g_z[(size_t)tt*DI + gd];
        g_gate[(size_t)tt*DI + gd] = sdt[idx] * siluf(z);
    }
}

// ---------------- launch ----------------
extern "C" void kernel_launch(void* const* d_in, const int* in_sizes, int n_in,
                              void* d_out, int out_size) {
    const int*   x     = (const int*)  d_in[0];
    const float* emb   = (const float*)d_in[1];
    const float* n1w   = (const float*)d_in[2];
    const float* n1b   = (const float*)d_in[3];
    const float* n2w   = (const float*)d_in[4];
    const float* n2b   = (const float*)d_in[5];
    const float* ipw   = (const float*)d_in[6];
    const float* cw    = (const float*)d_in[7];
    const float* cb    = (const float*)d_in[8];
    const float* xpw   = (const float*)d_in[9];
    const float* dpw   = (const float*)d_in[10];
    const float* dpb   = (const float*)d_in[11];
    const float* alog  = (const float*)d_in[12];
    const float* dskip = (const float*)d_in[13];
    const float* opw   = (const float*)d_in[14];
    const float* aiw   = (const float*)d_in[15];
    const float* aib   = (const float*)d_in[16];
    const float* aow   = (const float*)d_in[17];
    const float* aob   = (const float*)d_in[18];
    const float* nfw   = (const float*)d_in[19];
    const float* nfb   = (const float*)d_in[20];
    const float* headb = (const float*)d_in[21];
    float* out = (float*)d_out;

    float* ph;    cudaGetSymbolAddress((void**)&ph, g_h);
    float* ph2;   cudaGetSymbolAddress((void**)&ph2, g_h2);
    float* pz;    cudaGetSymbolAddress((void**)&pz, g_z);
    float* pu;    cudaGetSymbolAddress((void**)&pu, g_u);
    float* pgate; cudaGetSymbolAddress((void**)&pgate, g_gate);
    float* pwc;   cudaGetSymbolAddress((void**)&pwc, g_wc);
    float* pbc;   cudaGetSymbolAddress((void**)&pbc, g_bc);
    unsigned* pbar; cudaGetSymbolAddress((void**)&pbar, g_bar);

    cudaMemsetAsync(pbar, 0, sizeof(unsigned));

    // prep: combined attn weights/biases + embed, one launch
    k_prep<<<dim3(16, 1, 7), 256>>>(x, emb, aiw, aib, aow, aob);

    float* hc = ph;
    float* hn = ph2;

    for (int i = 0; i < NLAYER; i++) {
        const float* L_n1w = n1w + i*DMODEL;
        const float* L_n1b = n1b + i*DMODEL;
        const float* L_n2w = n2w + i*DMODEL;
        const float* L_n2b = n2b + i*DMODEL;
        const float* L_ipw = ipw + (size_t)i*2*DI*DMODEL;
        const float* L_cw  = cw  + (size_t)i*DI*DC;
        const float* L_cb  = cb  + (size_t)i*DI;
        const float* L_xpw = xpw + (size_t)i*XDW*DI;
        const float* L_dpw = dpw + (size_t)i*DI*DTR;
        const float* L_dpb = dpb + (size_t)i*DI;
        const float* L_alog= alog+ (size_t)i*DI*DS;
        const float* L_skip= dskip+(size_t)i*DI;
        const float* L_opw = opw + (size_t)i*DMODEL*DI;
        const float* L_wc  = pwc + (size_t)i*DMODEL*DMODEL;
        const float* L_bc  = pbc + (size_t)i*DMODEL;

        // in_proj (LN1 fused) + conv+silu (u) / z
        k_gemm_tc<128><<<dim3((2*DI)/TBN, 1), 256>>>(
            hc, DMODEL, L_ipw, DMODEL, nullptr, nullptr, 0,
            LSEQ, 2*DI, DMODEL, 0, 3, L_n1w, L_n1b, 1, L_cw, L_cb, pu, pz, nullptr);
        // x_proj + dt-proj + scan + gate, one launch (internal slab barrier)
        k_scanmega<<<NSLAB, 512>>>(i, L_xpw, L_alog, L_skip, L_dpw, L_dpb);
        // h += gate @ opw^T
        k_gemm_tc<64><<<dim3(DMODEL/TBN, LSEQ/64), 128>>>(
            pgate, DI, L_opw, DI, nullptr, hc, DMODEL,
            LSEQ, DMODEL, DI, 0, 1, nullptr, nullptr, 0,
            nullptr, nullptr, nullptr, nullptr, nullptr);
        // combined attention: hn = hc + LN2(hc) @ Wc^T + bc
        k_gemm_tc<64><<<dim3(DMODEL/TBN, LSEQ/64), 128>>>(
            hc, DMODEL, L_wc, DMODEL, L_bc, hn, DMODEL,
            LSEQ, DMODEL, DMODEL, 0, 4, L_n2w, L_n2b, 1,
            nullptr, nullptr, nullptr, nullptr, hc);
        float* tmp = hc; hc = hn; hn = tmp;
    }

    // head with final LN fused in prologue
    k_gemm_tc<128><<<dim3(VOCAB/TBN, 1), 256>>>(
        hc, DMODEL, emb, DMODEL, headb, out, VOCAB,
        LSEQ, VOCAB, DMODEL, 0, 0, nfw, nfb, 1,
        nullptr, nullptr, nullptr, nullptr, nullptr);
}